// round 2
// baseline (speedup 1.0000x reference)
#include <cuda_runtime.h>

// ---------------- problem dims ----------------
constexpr int NTOK   = 4096;   // B*S
constexpr int BATCH  = 2;
constexpr int SEQ    = 2048;
constexpr int DM     = 1024;
constexpr int NH     = 16;
constexpr int INTER_ = 4096;

constexpr size_t SZ_D  = (size_t)NTOK * DM;      // 4M floats
constexpr size_t SZ_R  = (size_t)NTOK * 512;     // 2M floats
constexpr size_t SZ_FF = (size_t)NTOK * INTER_;  // 16M floats

constexpr size_t OFF_NORMED = 0;
constexpr size_t OFF_TQ = OFF_NORMED + SZ_D;
constexpr size_t OFF_TK = OFF_TQ + SZ_R;
constexpr size_t OFF_TV = OFF_TK + SZ_R;
constexpr size_t OFF_Q  = OFF_TV + SZ_R;
constexpr size_t OFF_K  = OFF_Q + SZ_D;
constexpr size_t OFF_V  = OFF_K + SZ_D;
constexpr size_t OFF_AT = OFF_V + SZ_D;
constexpr size_t OFF_T1 = OFF_AT + SZ_D;
constexpr size_t OFF_H  = OFF_T1 + SZ_R;
constexpr size_t OFF_N2 = OFF_H + SZ_D;
constexpr size_t OFF_FF = OFF_N2 + SZ_D;
constexpr size_t BUF_TOTAL = OFF_FF + SZ_FF;     // 52M floats = 208 MB

__device__ float g_buf[BUF_TOTAL];

// ---------------- LayerNorm ----------------
__global__ void ln_kernel(const float* __restrict__ x, const float* __restrict__ w,
                          const float* __restrict__ b, float* __restrict__ y) {
    int row = blockIdx.x;
    const float* xr = x + (size_t)row * DM;
    float* yr = y + (size_t)row * DM;
    int t = threadIdx.x;               // 256 threads, 4 elems each
    float v[4]; float s = 0.f, ss = 0.f;
#pragma unroll
    for (int i = 0; i < 4; i++) {
        float val = xr[t + i * 256];
        v[i] = val; s += val; ss += val * val;
    }
#pragma unroll
    for (int o = 16; o > 0; o >>= 1) {
        s  += __shfl_xor_sync(0xffffffffu, s, o);
        ss += __shfl_xor_sync(0xffffffffu, ss, o);
    }
    __shared__ float rs[8], rss[8];
    int warp = t >> 5, lane = t & 31;
    if (lane == 0) { rs[warp] = s; rss[warp] = ss; }
    __syncthreads();
    float tot = 0.f, tot2 = 0.f;
#pragma unroll
    for (int i = 0; i < 8; i++) { tot += rs[i]; tot2 += rss[i]; }
    float mean = tot * (1.0f / DM);
    float var  = tot2 * (1.0f / DM) - mean * mean;
    float inv  = rsqrtf(var + 1e-5f);
#pragma unroll
    for (int i = 0; i < 4; i++) {
        int c = t + i * 256;
        yr[c] = (v[i] - mean) * inv * w[c] + b[c];
    }
}

// ---------------- generic SGEMM: C[M,N] = A[M,K] @ W[N,K]^T ----------------
__device__ __forceinline__ float gelu_exact(float x) {
    return 0.5f * x * (1.0f + erff(x * 0.7071067811865476f));
}

// EPI: 0 none, 1 +bias, 2 +bias+res, 3 gelu(acc+bias)
template<int EPI>
__global__ __launch_bounds__(256, 2)
void sgemm_kernel(const float* __restrict__ A, const float* __restrict__ W,
                  const float* __restrict__ bias, const float* __restrict__ res,
                  float* __restrict__ C, int M, int N, int K) {
    __shared__ __align__(16) float As[2][8][128];
    __shared__ __align__(16) float Bs[2][8][128];
    int bm = blockIdx.y * 128, bn = blockIdx.x * 128;
    int t = threadIdx.x;
    int lrow = t >> 1, lcol = (t & 1) * 4;
    const float* Ap = A + (size_t)(bm + lrow) * K + lcol;
    const float* Bp = W + (size_t)(bn + lrow) * K + lcol;
    int ty = t >> 4, tx = t & 15;
    float acc[8][8];
#pragma unroll
    for (int i = 0; i < 8; i++)
#pragma unroll
        for (int j = 0; j < 8; j++) acc[i][j] = 0.f;

    float4 a4 = *(const float4*)Ap;
    float4 b4 = *(const float4*)Bp;
    As[0][lcol + 0][lrow] = a4.x; As[0][lcol + 1][lrow] = a4.y;
    As[0][lcol + 2][lrow] = a4.z; As[0][lcol + 3][lrow] = a4.w;
    Bs[0][lcol + 0][lrow] = b4.x; Bs[0][lcol + 1][lrow] = b4.y;
    Bs[0][lcol + 2][lrow] = b4.z; Bs[0][lcol + 3][lrow] = b4.w;
    __syncthreads();
    int buf = 0;
    for (int k0 = 0; k0 < K; k0 += 8) {
        bool has_next = (k0 + 8) < K;
        if (has_next) {
            a4 = *(const float4*)(Ap + k0 + 8);
            b4 = *(const float4*)(Bp + k0 + 8);
        }
#pragma unroll
        for (int kk = 0; kk < 8; kk++) {
            float4 ar0 = *(const float4*)&As[buf][kk][ty * 8];
            float4 ar1 = *(const float4*)&As[buf][kk][ty * 8 + 4];
            float4 br0 = *(const float4*)&Bs[buf][kk][tx * 8];
            float4 br1 = *(const float4*)&Bs[buf][kk][tx * 8 + 4];
            float a[8]  = {ar0.x, ar0.y, ar0.z, ar0.w, ar1.x, ar1.y, ar1.z, ar1.w};
            float bb[8] = {br0.x, br0.y, br0.z, br0.w, br1.x, br1.y, br1.z, br1.w};
#pragma unroll
            for (int i = 0; i < 8; i++)
#pragma unroll
                for (int j = 0; j < 8; j++) acc[i][j] += a[i] * bb[j];
        }
        if (has_next) {
            int nb = buf ^ 1;
            As[nb][lcol + 0][lrow] = a4.x; As[nb][lcol + 1][lrow] = a4.y;
            As[nb][lcol + 2][lrow] = a4.z; As[nb][lcol + 3][lrow] = a4.w;
            Bs[nb][lcol + 0][lrow] = b4.x; Bs[nb][lcol + 1][lrow] = b4.y;
            Bs[nb][lcol + 2][lrow] = b4.z; Bs[nb][lcol + 3][lrow] = b4.w;
            __syncthreads();
            buf = nb;
        }
    }
#pragma unroll
    for (int i = 0; i < 8; i++) {
        size_t row = (size_t)(bm + ty * 8 + i);
        float* crow = C + row * N + bn + tx * 8;
        const float* rrow = (EPI == 2) ? (res + row * N + bn + tx * 8) : nullptr;
#pragma unroll
        for (int j = 0; j < 8; j++) {
            float vout = acc[i][j];
            if (EPI >= 1) vout += bias[bn + tx * 8 + j];
            if (EPI == 3) vout = gelu_exact(vout);
            if (EPI == 2) vout += rrow[j];
            crow[j] = vout;
        }
    }
}

// Batched variant for QKV stage 1: z selects (W, C) pair. Same inner loop.
__global__ __launch_bounds__(256, 2)
void sgemm3_kernel(const float* __restrict__ A,
                   const float* __restrict__ W0, const float* __restrict__ W1,
                   const float* __restrict__ W2,
                   float* __restrict__ C0, float* __restrict__ C1, float* __restrict__ C2,
                   int M, int N, int K) {
    const float* W = (blockIdx.z == 0) ? W0 : (blockIdx.z == 1) ? W1 : W2;
    float* C       = (blockIdx.z == 0) ? C0 : (blockIdx.z == 1) ? C1 : C2;
    __shared__ __align__(16) float As[2][8][128];
    __shared__ __align__(16) float Bs[2][8][128];
    int bm = blockIdx.y * 128, bn = blockIdx.x * 128;
    int t = threadIdx.x;
    int lrow = t >> 1, lcol = (t & 1) * 4;
    const float* Ap = A + (size_t)(bm + lrow) * K + lcol;
    const float* Bp = W + (size_t)(bn + lrow) * K + lcol;
    int ty = t >> 4, tx = t & 15;
    float acc[8][8];
#pragma unroll
    for (int i = 0; i < 8; i++)
#pragma unroll
        for (int j = 0; j < 8; j++) acc[i][j] = 0.f;
    float4 a4 = *(const float4*)Ap;
    float4 b4 = *(const float4*)Bp;
    As[0][lcol + 0][lrow] = a4.x; As[0][lcol + 1][lrow] = a4.y;
    As[0][lcol + 2][lrow] = a4.z; As[0][lcol + 3][lrow] = a4.w;
    Bs[0][lcol + 0][lrow] = b4.x; Bs[0][lcol + 1][lrow] = b4.y;
    Bs[0][lcol + 2][lrow] = b4.z; Bs[0][lcol + 3][lrow] = b4.w;
    __syncthreads();
    int buf = 0;
    for (int k0 = 0; k0 < K; k0 += 8) {
        bool has_next = (k0 + 8) < K;
        if (has_next) {
            a4 = *(const float4*)(Ap + k0 + 8);
            b4 = *(const float4*)(Bp + k0 + 8);
        }
#pragma unroll
        for (int kk = 0; kk < 8; kk++) {
            float4 ar0 = *(const float4*)&As[buf][kk][ty * 8];
            float4 ar1 = *(const float4*)&As[buf][kk][ty * 8 + 4];
            float4 br0 = *(const float4*)&Bs[buf][kk][tx * 8];
            float4 br1 = *(const float4*)&Bs[buf][kk][tx * 8 + 4];
            float a[8]  = {ar0.x, ar0.y, ar0.z, ar0.w, ar1.x, ar1.y, ar1.z, ar1.w};
            float bb[8] = {br0.x, br0.y, br0.z, br0.w, br1.x, br1.y, br1.z, br1.w};
#pragma unroll
            for (int i = 0; i < 8; i++)
#pragma unroll
                for (int j = 0; j < 8; j++) acc[i][j] += a[i] * bb[j];
        }
        if (has_next) {
            int nb = buf ^ 1;
            As[nb][lcol + 0][lrow] = a4.x; As[nb][lcol + 1][lrow] = a4.y;
            As[nb][lcol + 2][lrow] = a4.z; As[nb][lcol + 3][lrow] = a4.w;
            Bs[nb][lcol + 0][lrow] = b4.x; Bs[nb][lcol + 1][lrow] = b4.y;
            Bs[nb][lcol + 2][lrow] = b4.z; Bs[nb][lcol + 3][lrow] = b4.w;
            __syncthreads();
            buf = nb;
        }
    }
#pragma unroll
    for (int i = 0; i < 8; i++) {
        size_t row = (size_t)(bm + ty * 8 + i);
        float* crow = C + row * N + bn + tx * 8;
#pragma unroll
        for (int j = 0; j < 8; j++) crow[j] = acc[i][j];
    }
}

// ---------------- QKV stage 2: per-head [N,32]x[32,64] + bias + clamp ----------------
__global__ void qkv2_kernel(const float* __restrict__ Tq, const float* __restrict__ Tk,
                            const float* __restrict__ Tv,
                            const float* __restrict__ Uq, const float* __restrict__ Uk,
                            const float* __restrict__ Uv,
                            const float* __restrict__ bq, const float* __restrict__ bk,
                            const float* __restrict__ bv,
                            float* __restrict__ q, float* __restrict__ k, float* __restrict__ v) {
    int which = blockIdx.z;
    const float* T  = (which == 0) ? Tq : (which == 1) ? Tk : Tv;
    const float* U  = (which == 0) ? Uq : (which == 1) ? Uk : Uv;
    const float* bi = (which == 0) ? bq : (which == 1) ? bk : bv;
    float* outp     = (which == 0) ? q  : (which == 1) ? k  : v;
    int h = blockIdx.y;
    int tok0 = blockIdx.x * 16;
    __shared__ float Us[64][33];   // pad: avoid 32-way conflicts
    __shared__ float Ts[16][32];
    int t = threadIdx.x;
    for (int i = t; i < 64 * 32; i += 256) Us[i >> 5][i & 31] = U[(size_t)h * 2048 + i];
    for (int i = t; i < 16 * 32; i += 256)
        Ts[i >> 5][i & 31] = T[(size_t)(tok0 + (i >> 5)) * 512 + h * 32 + (i & 31)];
    __syncthreads();
    int e = t & 63, tg = t >> 6;
    float bsv = bi[h * 64 + e];
#pragma unroll
    for (int ti = 0; ti < 4; ti++) {
        int tok = tg * 4 + ti;
        float s = bsv;
#pragma unroll
        for (int r = 0; r < 32; r++) s += Ts[tok][r] * Us[e][r];
        s = fminf(fmaxf(s, -1.0e6f), 1.0e6f);
        int gtok = tok0 + tok;
        int bb = gtok >> 11;      // / SEQ
        int ss = gtok & 2047;     // % SEQ
        outp[(((size_t)bb * NH + h) * SEQ + ss) * 64 + e] = s;
    }
}

// ---------------- causal flash attention (fp32, Br=64, Bc=32, HD=64) ----------------
__global__ __launch_bounds__(256)
void attn_kernel(const float* __restrict__ q, const float* __restrict__ k,
                 const float* __restrict__ v, float* __restrict__ o) {
    int qt = blockIdx.x, h = blockIdx.y, b = blockIdx.z;
    const size_t base = (((size_t)b * NH + h) * SEQ) * 64;
    __shared__ __align__(16) float Qs[64][64];  // [e][r]
    __shared__ __align__(16) float Ks[64][32];  // [e][c]
    __shared__ __align__(16) float Vs[32][64];  // [c][e]
    __shared__ __align__(16) float Ps[64][32];  // [r][c]
    int t = threadIdx.x;
    int tx = t & 15, ty = t >> 4;
    int ty4 = ty * 4, tx4 = tx * 4, tx2 = tx * 2;
    // load Q tile transposed
    {
        int r = t >> 2, e0 = (t & 3) * 16;
        const float4* src = (const float4*)(q + base + (size_t)(qt * 64 + r) * 64 + e0);
#pragma unroll
        for (int i = 0; i < 4; i++) {
            float4 val = src[i];
            int e = e0 + i * 4;
            Qs[e][r] = val.x; Qs[e + 1][r] = val.y; Qs[e + 2][r] = val.z; Qs[e + 3][r] = val.w;
        }
    }
    float m[4], l[4], acc[4][4];
#pragma unroll
    for (int i = 0; i < 4; i++) {
        m[i] = -1e30f; l[i] = 0.f;
#pragma unroll
        for (int j = 0; j < 4; j++) acc[i][j] = 0.f;
    }
    int qrow0 = qt * 64 + ty4;
    int ntiles = 2 * qt + 2;               // 32-wide kv tiles, causal
    for (int j = 0; j < ntiles; j++) {
        __syncthreads();                    // protect smem reuse (also fences Q load, iter 0)
        {
            int r = t >> 3, e0 = (t & 7) * 8;   // 32 rows x 64 dims, 8 floats/thread
            const float4* ksrc = (const float4*)(k + base + (size_t)(j * 32 + r) * 64 + e0);
            const float4* vsrc = (const float4*)(v + base + (size_t)(j * 32 + r) * 64 + e0);
#pragma unroll
            for (int i = 0; i < 2; i++) {
                float4 kv = ksrc[i];
                int e = e0 + i * 4;
                Ks[e][r] = kv.x; Ks[e + 1][r] = kv.y; Ks[e + 2][r] = kv.z; Ks[e + 3][r] = kv.w;
                float4 vv = vsrc[i];
                *(float4*)&Vs[r][e] = vv;
            }
        }
        __syncthreads();
        // scores: 4 rows x 2 cols per thread
        float s[4][2];
#pragma unroll
        for (int i = 0; i < 4; i++) { s[i][0] = 0.f; s[i][1] = 0.f; }
#pragma unroll
        for (int e = 0; e < 64; e++) {
            float4 qa = *(const float4*)&Qs[e][ty4];
            float2 kb = *(const float2*)&Ks[e][tx2];
            float av[4] = {qa.x, qa.y, qa.z, qa.w};
#pragma unroll
            for (int i = 0; i < 4; i++) {
                s[i][0] += av[i] * kb.x;
                s[i][1] += av[i] * kb.y;
            }
        }
        int col0 = j * 32 + tx2;
        float rmax[4];
#pragma unroll
        for (int i = 0; i < 4; i++) {
            float mx = -1e30f;
#pragma unroll
            for (int jj = 0; jj < 2; jj++) {
                float val = s[i][jj] * 0.125f;                // 1/sqrt(64)
                if (col0 + jj > qrow0 + i) val = -1e30f;      // causal mask
                s[i][jj] = val;
                mx = fmaxf(mx, val);
            }
            rmax[i] = mx;
        }
#pragma unroll
        for (int o_ = 1; o_ < 16; o_ <<= 1)
#pragma unroll
            for (int i = 0; i < 4; i++)
                rmax[i] = fmaxf(rmax[i], __shfl_xor_sync(0xffffffffu, rmax[i], o_));
        float corr[4], rsum[4];
#pragma unroll
        for (int i = 0; i < 4; i++) {
            float mn = fmaxf(m[i], rmax[i]);
            corr[i] = __expf(m[i] - mn);
            m[i] = mn;
            float rsu = 0.f;
#pragma unroll
            for (int jj = 0; jj < 2; jj++) {
                float p = __expf(s[i][jj] - mn);
                s[i][jj] = p; rsu += p;
            }
            rsum[i] = rsu;
        }
#pragma unroll
        for (int o_ = 1; o_ < 16; o_ <<= 1)
#pragma unroll
            for (int i = 0; i < 4; i++)
                rsum[i] += __shfl_xor_sync(0xffffffffu, rsum[i], o_);
#pragma unroll
        for (int i = 0; i < 4; i++) {
            l[i] = l[i] * corr[i] + rsum[i];
#pragma unroll
            for (int jj = 0; jj < 4; jj++) acc[i][jj] *= corr[i];
        }
#pragma unroll
        for (int i = 0; i < 4; i++)
            *(float2*)&Ps[ty4 + i][tx2] = make_float2(s[i][0], s[i][1]);
        __syncthreads();
        // PV: acc[i][jj] += sum_c Ps[r][c] * Vs[c][e]
#pragma unroll 8
        for (int c = 0; c < 32; c++) {
            float pp[4] = {Ps[ty4 + 0][c], Ps[ty4 + 1][c], Ps[ty4 + 2][c], Ps[ty4 + 3][c]};
            float4 vv = *(const float4*)&Vs[c][tx4];
            float vvv[4] = {vv.x, vv.y, vv.z, vv.w};
#pragma unroll
            for (int i = 0; i < 4; i++)
#pragma unroll
                for (int jj = 0; jj < 4; jj++) acc[i][jj] += pp[i] * vvv[jj];
        }
    }
#pragma unroll
    for (int i = 0; i < 4; i++) {
        float inv = 1.0f / l[i];
        size_t off = (size_t)(b * SEQ + qt * 64 + ty4 + i) * DM + h * 64 + tx4;
        float4 ov = make_float4(acc[i][0] * inv, acc[i][1] * inv, acc[i][2] * inv, acc[i][3] * inv);
        *(float4*)(o + off) = ov;
    }
}

// ---------------- launch ----------------
extern "C" void kernel_launch(void* const* d_in, const int* in_sizes, int n_in,
                              void* d_out, int out_size) {
    const float* hidden = (const float*)d_in[0];
    const float* q_U    = (const float*)d_in[1];
    const float* q_V    = (const float*)d_in[2];
    const float* q_b    = (const float*)d_in[3];
    const float* k_U    = (const float*)d_in[4];
    const float* k_V    = (const float*)d_in[5];
    const float* k_b    = (const float*)d_in[6];
    const float* v_U    = (const float*)d_in[7];
    const float* v_V    = (const float*)d_in[8];
    const float* v_b    = (const float*)d_in[9];
    const float* out_U  = (const float*)d_in[10];
    const float* out_V  = (const float*)d_in[11];
    const float* out_b  = (const float*)d_in[12];
    const float* fc1_U  = (const float*)d_in[13];
    const float* fc1_V  = (const float*)d_in[14];
    const float* fc1_b  = (const float*)d_in[15];
    const float* fc2_U  = (const float*)d_in[16];
    const float* fc2_V  = (const float*)d_in[17];
    const float* fc2_b  = (const float*)d_in[18];
    const float* ln1w   = (const float*)d_in[19];
    const float* ln1b   = (const float*)d_in[20];
    const float* ln2w   = (const float*)d_in[21];
    const float* ln2b   = (const float*)d_in[22];
    float* out = (float*)d_out;

    float* buf = nullptr;
    cudaGetSymbolAddress((void**)&buf, g_buf);
    float* normed = buf + OFF_NORMED;
    float* Tq = buf + OFF_TQ;  float* Tk = buf + OFF_TK;  float* Tv = buf + OFF_TV;
    float* qd = buf + OFF_Q;   float* kd = buf + OFF_K;   float* vd = buf + OFF_V;
    float* att = buf + OFF_AT;
    float* t1  = buf + OFF_T1;
    float* hb  = buf + OFF_H;
    float* n2  = buf + OFF_N2;
    float* ff  = buf + OFF_FF;
    float* t3  = Tq;                        // reuse: Tq dead after qkv2

    dim3 gr_r(512 / 128, NTOK / 128);        // N=512 GEMMs
    dim3 gr_r3(512 / 128, NTOK / 128, 3);    // fused QKV stage 1
    dim3 gr_d(DM / 128, NTOK / 128);         // N=1024 GEMMs
    dim3 gr_f(INTER_ / 128, NTOK / 128);     // N=4096 GEMM

    // 1) LN1
    ln_kernel<<<NTOK, 256>>>(hidden, ln1w, ln1b, normed);
    // 2) QKV low-rank stage 1: T = normed @ V^T  (V flat [H*RA, D]) — one launch
    sgemm3_kernel<<<gr_r3, 256>>>(normed, q_V, k_V, v_V, Tq, Tk, Tv, NTOK, 512, DM);
    // 3) QKV stage 2 (+bias, clamp) -> [B,H,S,HD]
    qkv2_kernel<<<dim3(NTOK / 16, NH, 3), 256>>>(Tq, Tk, Tv, q_U, k_U, v_U,
                                                 q_b, k_b, v_b, qd, kd, vd);
    // 4) causal flash attention -> [B*S, D]
    attn_kernel<<<dim3(SEQ / 64, NH, BATCH), 256>>>(qd, kd, vd, att);
    // 5) out projection + residual
    sgemm_kernel<0><<<gr_r, 256>>>(att, out_V, nullptr, nullptr, t1, NTOK, 512, DM);
    sgemm_kernel<2><<<gr_d, 256>>>(t1, out_U, out_b, hidden, hb, NTOK, DM, 512);
    // 6) LN2
    ln_kernel<<<NTOK, 256>>>(hb, ln2w, ln2b, n2);
    // 7) FFN
    sgemm_kernel<0><<<gr_r, 256>>>(n2, fc1_V, nullptr, nullptr, t1, NTOK, 512, DM);
    sgemm_kernel<3><<<gr_f, 256>>>(t1, fc1_U, fc1_b, nullptr, ff, NTOK, INTER_, 512);
    sgemm_kernel<0><<<gr_r, 256>>>(ff, fc2_V, nullptr, nullptr, t3, NTOK, 512, INTER_);
    sgemm_kernel<2><<<gr_d, 256>>>(t3, fc2_U, fc2_b, hb, out, NTOK, DM, 512);
}

// round 4
// speedup vs baseline: 1.5345x; 1.5345x over previous
#include <cuda_runtime.h>

// Round 4 = round 3 resubmission: TF32 tensor-core GEMMs (untested due to
// container infra failure). Attention intentionally untouched for attribution.

// ---------------- problem dims ----------------
constexpr int NTOK   = 4096;   // B*S
constexpr int BATCH  = 2;
constexpr int SEQ    = 2048;
constexpr int DM     = 1024;
constexpr int NH     = 16;
constexpr int INTER_ = 4096;

constexpr size_t SZ_D  = (size_t)NTOK * DM;
constexpr size_t SZ_R  = (size_t)NTOK * 512;
constexpr size_t SZ_FF = (size_t)NTOK * INTER_;

constexpr size_t OFF_NORMED = 0;
constexpr size_t OFF_TQ = OFF_NORMED + SZ_D;
constexpr size_t OFF_TK = OFF_TQ + SZ_R;
constexpr size_t OFF_TV = OFF_TK + SZ_R;
constexpr size_t OFF_Q  = OFF_TV + SZ_R;
constexpr size_t OFF_K  = OFF_Q + SZ_D;
constexpr size_t OFF_V  = OFF_K + SZ_D;
constexpr size_t OFF_AT = OFF_V + SZ_D;
constexpr size_t OFF_T1 = OFF_AT + SZ_D;
constexpr size_t OFF_H  = OFF_T1 + SZ_R;
constexpr size_t OFF_N2 = OFF_H + SZ_D;
constexpr size_t OFF_FF = OFF_N2 + SZ_D;
constexpr size_t BUF_TOTAL = OFF_FF + SZ_FF;

__device__ float g_buf[BUF_TOTAL];

// ---------------- helpers ----------------
__device__ __forceinline__ float gelu_exact(float x) {
    return 0.5f * x * (1.0f + erff(x * 0.7071067811865476f));
}
__device__ __forceinline__ float tf32r(float f) {
    unsigned u;
    asm("cvt.rna.tf32.f32 %0, %1;" : "=r"(u) : "f"(f));
    return __uint_as_float(u);
}
__device__ __forceinline__ void mma_tf32(float* c, const unsigned* a, const unsigned* b) {
    asm volatile(
        "mma.sync.aligned.m16n8k8.row.col.f32.tf32.tf32.f32 "
        "{%0,%1,%2,%3}, {%4,%5,%6,%7}, {%8,%9}, {%0,%1,%2,%3};"
        : "+f"(c[0]), "+f"(c[1]), "+f"(c[2]), "+f"(c[3])
        : "r"(a[0]), "r"(a[1]), "r"(a[2]), "r"(a[3]), "r"(b[0]), "r"(b[1]));
}

// ---------------- LayerNorm ----------------
__global__ void ln_kernel(const float* __restrict__ x, const float* __restrict__ w,
                          const float* __restrict__ b, float* __restrict__ y) {
    int row = blockIdx.x;
    const float* xr = x + (size_t)row * DM;
    float* yr = y + (size_t)row * DM;
    int t = threadIdx.x;
    float v[4]; float s = 0.f, ss = 0.f;
#pragma unroll
    for (int i = 0; i < 4; i++) {
        float val = xr[t + i * 256];
        v[i] = val; s += val; ss += val * val;
    }
#pragma unroll
    for (int o = 16; o > 0; o >>= 1) {
        s  += __shfl_xor_sync(0xffffffffu, s, o);
        ss += __shfl_xor_sync(0xffffffffu, ss, o);
    }
    __shared__ float rs[8], rss[8];
    int warp = t >> 5, lane = t & 31;
    if (lane == 0) { rs[warp] = s; rss[warp] = ss; }
    __syncthreads();
    float tot = 0.f, tot2 = 0.f;
#pragma unroll
    for (int i = 0; i < 8; i++) { tot += rs[i]; tot2 += rss[i]; }
    float mean = tot * (1.0f / DM);
    float var  = tot2 * (1.0f / DM) - mean * mean;
    float inv  = rsqrtf(var + 1e-5f);
#pragma unroll
    for (int i = 0; i < 4; i++) {
        int c = t + i * 256;
        yr[c] = (v[i] - mean) * inv * w[c] + b[c];
    }
}

// ---------------- TF32 tensor-core GEMM core ----------------
// C[M,N] = A[M,K] @ W[N,K]^T ; block 128x128, 8 warps (2x4), warp tile 64x32,
// k-slab 8, double-buffered. smem stride 136 => fragment loads conflict-free.
// EPI: 0 none, 1 +bias, 2 +bias+res, 3 gelu(acc+bias)
template<int EPI>
__device__ __forceinline__ void gemm_tf32_core(
    const float* __restrict__ A, const float* __restrict__ W,
    const float* __restrict__ bias, const float* __restrict__ res,
    float* __restrict__ C, int M, int N, int K, int bm, int bn) {
    __shared__ float As[2][8][136];
    __shared__ float Bs[2][8][136];
    int t = threadIdx.x;
    int lrow = t >> 1, lcol = (t & 1) * 4;
    const float* Ap = A + (size_t)(bm + lrow) * K + lcol;
    const float* Bp = W + (size_t)(bn + lrow) * K + lcol;

    int wid = t >> 5, lane = t & 31;
    int wm = (wid & 1) * 64, wn = (wid >> 1) * 32;
    int g = lane >> 2, t4 = lane & 3;

    float acc[4][4][4];
#pragma unroll
    for (int mi = 0; mi < 4; mi++)
#pragma unroll
        for (int ni = 0; ni < 4; ni++)
#pragma unroll
            for (int r = 0; r < 4; r++) acc[mi][ni][r] = 0.f;

    float4 a4 = *(const float4*)Ap;
    float4 b4 = *(const float4*)Bp;
    As[0][lcol + 0][lrow] = tf32r(a4.x); As[0][lcol + 1][lrow] = tf32r(a4.y);
    As[0][lcol + 2][lrow] = tf32r(a4.z); As[0][lcol + 3][lrow] = tf32r(a4.w);
    Bs[0][lcol + 0][lrow] = tf32r(b4.x); Bs[0][lcol + 1][lrow] = tf32r(b4.y);
    Bs[0][lcol + 2][lrow] = tf32r(b4.z); Bs[0][lcol + 3][lrow] = tf32r(b4.w);
    __syncthreads();
    int buf = 0;
    for (int k0 = 0; k0 < K; k0 += 8) {
        bool has_next = (k0 + 8) < K;
        if (has_next) {
            a4 = *(const float4*)(Ap + k0 + 8);
            b4 = *(const float4*)(Bp + k0 + 8);
        }
        unsigned af[4][4], bf[4][2];
#pragma unroll
        for (int mi = 0; mi < 4; mi++) {
            int m = wm + mi * 16 + g;
            af[mi][0] = __float_as_uint(As[buf][t4][m]);
            af[mi][1] = __float_as_uint(As[buf][t4][m + 8]);
            af[mi][2] = __float_as_uint(As[buf][t4 + 4][m]);
            af[mi][3] = __float_as_uint(As[buf][t4 + 4][m + 8]);
        }
#pragma unroll
        for (int ni = 0; ni < 4; ni++) {
            int n = wn + ni * 8 + g;
            bf[ni][0] = __float_as_uint(Bs[buf][t4][n]);
            bf[ni][1] = __float_as_uint(Bs[buf][t4 + 4][n]);
        }
#pragma unroll
        for (int mi = 0; mi < 4; mi++)
#pragma unroll
            for (int ni = 0; ni < 4; ni++)
                mma_tf32(acc[mi][ni], af[mi], bf[ni]);
        if (has_next) {
            int nb = buf ^ 1;
            As[nb][lcol + 0][lrow] = tf32r(a4.x); As[nb][lcol + 1][lrow] = tf32r(a4.y);
            As[nb][lcol + 2][lrow] = tf32r(a4.z); As[nb][lcol + 3][lrow] = tf32r(a4.w);
            Bs[nb][lcol + 0][lrow] = tf32r(b4.x); Bs[nb][lcol + 1][lrow] = tf32r(b4.y);
            Bs[nb][lcol + 2][lrow] = tf32r(b4.z); Bs[nb][lcol + 3][lrow] = tf32r(b4.w);
            __syncthreads();
            buf = nb;
        }
    }
#pragma unroll
    for (int mi = 0; mi < 4; mi++) {
        int r0 = bm + wm + mi * 16 + g;
#pragma unroll
        for (int ni = 0; ni < 4; ni++) {
            int col = bn + wn + ni * 8 + t4 * 2;
            float b0 = 0.f, b1 = 0.f;
            if (EPI >= 1) {
                float2 bb = *(const float2*)(bias + col);
                b0 = bb.x; b1 = bb.y;
            }
            float v00 = acc[mi][ni][0] + b0, v01 = acc[mi][ni][1] + b1;
            float v10 = acc[mi][ni][2] + b0, v11 = acc[mi][ni][3] + b1;
            if (EPI == 3) {
                v00 = gelu_exact(v00); v01 = gelu_exact(v01);
                v10 = gelu_exact(v10); v11 = gelu_exact(v11);
            }
            if (EPI == 2) {
                float2 r0v = *(const float2*)(res + (size_t)r0 * N + col);
                float2 r1v = *(const float2*)(res + (size_t)(r0 + 8) * N + col);
                v00 += r0v.x; v01 += r0v.y; v10 += r1v.x; v11 += r1v.y;
            }
            *(float2*)(C + (size_t)r0 * N + col)       = make_float2(v00, v01);
            *(float2*)(C + (size_t)(r0 + 8) * N + col) = make_float2(v10, v11);
        }
    }
}

template<int EPI>
__global__ __launch_bounds__(256, 2)
void sgemm_tf32_kernel(const float* __restrict__ A, const float* __restrict__ W,
                       const float* __restrict__ bias, const float* __restrict__ res,
                       float* __restrict__ C, int M, int N, int K) {
    gemm_tf32_core<EPI>(A, W, bias, res, C, M, N, K, blockIdx.y * 128, blockIdx.x * 128);
}

__global__ __launch_bounds__(256, 2)
void sgemm3_tf32_kernel(const float* __restrict__ A,
                        const float* __restrict__ W0, const float* __restrict__ W1,
                        const float* __restrict__ W2,
                        float* __restrict__ C0, float* __restrict__ C1, float* __restrict__ C2,
                        int M, int N, int K) {
    const float* W = (blockIdx.z == 0) ? W0 : (blockIdx.z == 1) ? W1 : W2;
    float* C       = (blockIdx.z == 0) ? C0 : (blockIdx.z == 1) ? C1 : C2;
    gemm_tf32_core<0>(A, W, nullptr, nullptr, C, M, N, K, blockIdx.y * 128, blockIdx.x * 128);
}

// ---------------- QKV stage 2: per-head [N,32]x[32,64] + bias + clamp ----------------
__global__ void qkv2_kernel(const float* __restrict__ Tq, const float* __restrict__ Tk,
                            const float* __restrict__ Tv,
                            const float* __restrict__ Uq, const float* __restrict__ Uk,
                            const float* __restrict__ Uv,
                            const float* __restrict__ bq, const float* __restrict__ bk,
                            const float* __restrict__ bv,
                            float* __restrict__ q, float* __restrict__ k, float* __restrict__ v) {
    int which = blockIdx.z;
    const float* T  = (which == 0) ? Tq : (which == 1) ? Tk : Tv;
    const float* U  = (which == 0) ? Uq : (which == 1) ? Uk : Uv;
    const float* bi = (which == 0) ? bq : (which == 1) ? bk : bv;
    float* outp     = (which == 0) ? q  : (which == 1) ? k  : v;
    int h = blockIdx.y;
    int tok0 = blockIdx.x * 16;
    __shared__ float Us[64][33];
    __shared__ float Ts[16][32];
    int t = threadIdx.x;
    for (int i = t; i < 64 * 32; i += 256) Us[i >> 5][i & 31] = U[(size_t)h * 2048 + i];
    for (int i = t; i < 16 * 32; i += 256)
        Ts[i >> 5][i & 31] = T[(size_t)(tok0 + (i >> 5)) * 512 + h * 32 + (i & 31)];
    __syncthreads();
    int e = t & 63, tg = t >> 6;
    float bsv = bi[h * 64 + e];
#pragma unroll
    for (int ti = 0; ti < 4; ti++) {
        int tok = tg * 4 + ti;
        float s = bsv;
#pragma unroll
        for (int r = 0; r < 32; r++) s += Ts[tok][r] * Us[e][r];
        s = fminf(fmaxf(s, -1.0e6f), 1.0e6f);
        int gtok = tok0 + tok;
        int bb = gtok >> 11;
        int ss = gtok & 2047;
        outp[(((size_t)bb * NH + h) * SEQ + ss) * 64 + e] = s;
    }
}

// ---------------- causal flash attention (fp32, Br=64, Bc=32, HD=64) ----------------
__global__ __launch_bounds__(256)
void attn_kernel(const float* __restrict__ q, const float* __restrict__ k,
                 const float* __restrict__ v, float* __restrict__ o) {
    int qt = blockIdx.x, h = blockIdx.y, b = blockIdx.z;
    const size_t base = (((size_t)b * NH + h) * SEQ) * 64;
    __shared__ __align__(16) float Qs[64][64];
    __shared__ __align__(16) float Ks[64][32];
    __shared__ __align__(16) float Vs[32][64];
    __shared__ __align__(16) float Ps[64][32];
    int t = threadIdx.x;
    int tx = t & 15, ty = t >> 4;
    int ty4 = ty * 4, tx4 = tx * 4, tx2 = tx * 2;
    {
        int r = t >> 2, e0 = (t & 3) * 16;
        const float4* src = (const float4*)(q + base + (size_t)(qt * 64 + r) * 64 + e0);
#pragma unroll
        for (int i = 0; i < 4; i++) {
            float4 val = src[i];
            int e = e0 + i * 4;
            Qs[e][r] = val.x; Qs[e + 1][r] = val.y; Qs[e + 2][r] = val.z; Qs[e + 3][r] = val.w;
        }
    }
    float m[4], l[4], acc[4][4];
#pragma unroll
    for (int i = 0; i < 4; i++) {
        m[i] = -1e30f; l[i] = 0.f;
#pragma unroll
        for (int j = 0; j < 4; j++) acc[i][j] = 0.f;
    }
    int qrow0 = qt * 64 + ty4;
    int ntiles = 2 * qt + 2;
    for (int j = 0; j < ntiles; j++) {
        __syncthreads();
        {
            int r = t >> 3, e0 = (t & 7) * 8;
            const float4* ksrc = (const float4*)(k + base + (size_t)(j * 32 + r) * 64 + e0);
            const float4* vsrc = (const float4*)(v + base + (size_t)(j * 32 + r) * 64 + e0);
#pragma unroll
            for (int i = 0; i < 2; i++) {
                float4 kv = ksrc[i];
                int e = e0 + i * 4;
                Ks[e][r] = kv.x; Ks[e + 1][r] = kv.y; Ks[e + 2][r] = kv.z; Ks[e + 3][r] = kv.w;
                float4 vv = vsrc[i];
                *(float4*)&Vs[r][e] = vv;
            }
        }
        __syncthreads();
        float s[4][2];
#pragma unroll
        for (int i = 0; i < 4; i++) { s[i][0] = 0.f; s[i][1] = 0.f; }
#pragma unroll
        for (int e = 0; e < 64; e++) {
            float4 qa = *(const float4*)&Qs[e][ty4];
            float2 kb = *(const float2*)&Ks[e][tx2];
            float av[4] = {qa.x, qa.y, qa.z, qa.w};
#pragma unroll
            for (int i = 0; i < 4; i++) {
                s[i][0] += av[i] * kb.x;
                s[i][1] += av[i] * kb.y;
            }
        }
        int col0 = j * 32 + tx2;
        float rmax[4];
#pragma unroll
        for (int i = 0; i < 4; i++) {
            float mx = -1e30f;
#pragma unroll
            for (int jj = 0; jj < 2; jj++) {
                float val = s[i][jj] * 0.125f;
                if (col0 + jj > qrow0 + i) val = -1e30f;
                s[i][jj] = val;
                mx = fmaxf(mx, val);
            }
            rmax[i] = mx;
        }
#pragma unroll
        for (int o_ = 1; o_ < 16; o_ <<= 1)
#pragma unroll
            for (int i = 0; i < 4; i++)
                rmax[i] = fmaxf(rmax[i], __shfl_xor_sync(0xffffffffu, rmax[i], o_));
        float corr[4], rsum[4];
#pragma unroll
        for (int i = 0; i < 4; i++) {
            float mn = fmaxf(m[i], rmax[i]);
            corr[i] = __expf(m[i] - mn);
            m[i] = mn;
            float rsu = 0.f;
#pragma unroll
            for (int jj = 0; jj < 2; jj++) {
                float p = __expf(s[i][jj] - mn);
                s[i][jj] = p; rsu += p;
            }
            rsum[i] = rsu;
        }
#pragma unroll
        for (int o_ = 1; o_ < 16; o_ <<= 1)
#pragma unroll
            for (int i = 0; i < 4; i++)
                rsum[i] += __shfl_xor_sync(0xffffffffu, rsum[i], o_);
#pragma unroll
        for (int i = 0; i < 4; i++) {
            l[i] = l[i] * corr[i] + rsum[i];
#pragma unroll
            for (int jj = 0; jj < 4; jj++) acc[i][jj] *= corr[i];
        }
#pragma unroll
        for (int i = 0; i < 4; i++)
            *(float2*)&Ps[ty4 + i][tx2] = make_float2(s[i][0], s[i][1]);
        __syncthreads();
#pragma unroll 8
        for (int c = 0; c < 32; c++) {
            float pp[4] = {Ps[ty4 + 0][c], Ps[ty4 + 1][c], Ps[ty4 + 2][c], Ps[ty4 + 3][c]};
            float4 vv = *(const float4*)&Vs[c][tx4];
            float vvv[4] = {vv.x, vv.y, vv.z, vv.w};
#pragma unroll
            for (int i = 0; i < 4; i++)
#pragma unroll
                for (int jj = 0; jj < 4; jj++) acc[i][jj] += pp[i] * vvv[jj];
        }
    }
#pragma unroll
    for (int i = 0; i < 4; i++) {
        float inv = 1.0f / l[i];
        size_t off = (size_t)(b * SEQ + qt * 64 + ty4 + i) * DM + h * 64 + tx4;
        float4 ov = make_float4(acc[i][0] * inv, acc[i][1] * inv, acc[i][2] * inv, acc[i][3] * inv);
        *(float4*)(o + off) = ov;
    }
}

// ---------------- launch ----------------
extern "C" void kernel_launch(void* const* d_in, const int* in_sizes, int n_in,
                              void* d_out, int out_size) {
    const float* hidden = (const float*)d_in[0];
    const float* q_U    = (const float*)d_in[1];
    const float* q_V    = (const float*)d_in[2];
    const float* q_b    = (const float*)d_in[3];
    const float* k_U    = (const float*)d_in[4];
    const float* k_V    = (const float*)d_in[5];
    const float* k_b    = (const float*)d_in[6];
    const float* v_U    = (const float*)d_in[7];
    const float* v_V    = (const float*)d_in[8];
    const float* v_b    = (const float*)d_in[9];
    const float* out_U  = (const float*)d_in[10];
    const float* out_V  = (const float*)d_in[11];
    const float* out_b  = (const float*)d_in[12];
    const float* fc1_U  = (const float*)d_in[13];
    const float* fc1_V  = (const float*)d_in[14];
    const float* fc1_b  = (const float*)d_in[15];
    const float* fc2_U  = (const float*)d_in[16];
    const float* fc2_V  = (const float*)d_in[17];
    const float* fc2_b  = (const float*)d_in[18];
    const float* ln1w   = (const float*)d_in[19];
    const float* ln1b   = (const float*)d_in[20];
    const float* ln2w   = (const float*)d_in[21];
    const float* ln2b   = (const float*)d_in[22];
    float* out = (float*)d_out;

    float* buf = nullptr;
    cudaGetSymbolAddress((void**)&buf, g_buf);
    float* normed = buf + OFF_NORMED;
    float* Tq = buf + OFF_TQ;  float* Tk = buf + OFF_TK;  float* Tv = buf + OFF_TV;
    float* qd = buf + OFF_Q;   float* kd = buf + OFF_K;   float* vd = buf + OFF_V;
    float* att = buf + OFF_AT;
    float* t1  = buf + OFF_T1;
    float* hb  = buf + OFF_H;
    float* n2  = buf + OFF_N2;
    float* ff  = buf + OFF_FF;
    float* t3  = Tq;                        // reuse: Tq dead after qkv2

    dim3 gr_r(512 / 128, NTOK / 128);
    dim3 gr_r3(512 / 128, NTOK / 128, 3);
    dim3 gr_d(DM / 128, NTOK / 128);
    dim3 gr_f(INTER_ / 128, NTOK / 128);

    ln_kernel<<<NTOK, 256>>>(hidden, ln1w, ln1b, normed);
    sgemm3_tf32_kernel<<<gr_r3, 256>>>(normed, q_V, k_V, v_V, Tq, Tk, Tv, NTOK, 512, DM);
    qkv2_kernel<<<dim3(NTOK / 16, NH, 3), 256>>>(Tq, Tk, Tv, q_U, k_U, v_U,
                                                 q_b, k_b, v_b, qd, kd, vd);
    attn_kernel<<<dim3(SEQ / 64, NH, BATCH), 256>>>(qd, kd, vd, att);
    sgemm_tf32_kernel<0><<<gr_r, 256>>>(att, out_V, nullptr, nullptr, t1, NTOK, 512, DM);
    sgemm_tf32_kernel<2><<<gr_d, 256>>>(t1, out_U, out_b, hidden, hb, NTOK, DM, 512);
    ln_kernel<<<NTOK, 256>>>(hb, ln2w, ln2b, n2);
    sgemm_tf32_kernel<0><<<gr_r, 256>>>(n2, fc1_V, nullptr, nullptr, t1, NTOK, 512, DM);
    sgemm_tf32_kernel<3><<<gr_f, 256>>>(t1, fc1_U, fc1_b, nullptr, ff, NTOK, INTER_, 512);
    sgemm_tf32_kernel<0><<<gr_r, 256>>>(ff, fc2_V, nullptr, nullptr, t3, NTOK, 512, INTER_);
    sgemm_tf32_kernel<2><<<gr_d, 256>>>(t3, fc2_U, fc2_b, hb, out, NTOK, DM, 512);
}

// round 5
// speedup vs baseline: 2.0213x; 1.3173x over previous
#include <cuda_runtime.h>

// Round 5: attention moved to TF32 tensor-core MMA (m16n8k8), same fragment
// mapping validated by the round-4 GEMM. GEMM side unchanged.

// ---------------- problem dims ----------------
constexpr int NTOK   = 4096;   // B*S
constexpr int BATCH  = 2;
constexpr int SEQ    = 2048;
constexpr int DM     = 1024;
constexpr int NH     = 16;
constexpr int INTER_ = 4096;

constexpr size_t SZ_D  = (size_t)NTOK * DM;
constexpr size_t SZ_R  = (size_t)NTOK * 512;
constexpr size_t SZ_FF = (size_t)NTOK * INTER_;

constexpr size_t OFF_NORMED = 0;
constexpr size_t OFF_TQ = OFF_NORMED + SZ_D;
constexpr size_t OFF_TK = OFF_TQ + SZ_R;
constexpr size_t OFF_TV = OFF_TK + SZ_R;
constexpr size_t OFF_Q  = OFF_TV + SZ_R;
constexpr size_t OFF_K  = OFF_Q + SZ_D;
constexpr size_t OFF_V  = OFF_K + SZ_D;
constexpr size_t OFF_AT = OFF_V + SZ_D;
constexpr size_t OFF_T1 = OFF_AT + SZ_D;
constexpr size_t OFF_H  = OFF_T1 + SZ_R;
constexpr size_t OFF_N2 = OFF_H + SZ_D;
constexpr size_t OFF_FF = OFF_N2 + SZ_D;
constexpr size_t BUF_TOTAL = OFF_FF + SZ_FF;

__device__ float g_buf[BUF_TOTAL];

// ---------------- helpers ----------------
__device__ __forceinline__ float gelu_exact(float x) {
    return 0.5f * x * (1.0f + erff(x * 0.7071067811865476f));
}
__device__ __forceinline__ float tf32r(float f) {
    unsigned u;
    asm("cvt.rna.tf32.f32 %0, %1;" : "=r"(u) : "f"(f));
    return __uint_as_float(u);
}
__device__ __forceinline__ void mma_tf32(float* c, const unsigned* a, const unsigned* b) {
    asm volatile(
        "mma.sync.aligned.m16n8k8.row.col.f32.tf32.tf32.f32 "
        "{%0,%1,%2,%3}, {%4,%5,%6,%7}, {%8,%9}, {%0,%1,%2,%3};"
        : "+f"(c[0]), "+f"(c[1]), "+f"(c[2]), "+f"(c[3])
        : "r"(a[0]), "r"(a[1]), "r"(a[2]), "r"(a[3]), "r"(b[0]), "r"(b[1]));
}
// XOR swizzle for 64-float rows: physical col = c ^ ((r&3)<<3). Keeps float4/2
// atoms intact (flips only bits 3-4) and spreads fragment loads across banks.
#define SW(r, c) ((c) ^ (((r) & 3) << 3))

// ---------------- LayerNorm ----------------
__global__ void ln_kernel(const float* __restrict__ x, const float* __restrict__ w,
                          const float* __restrict__ b, float* __restrict__ y) {
    int row = blockIdx.x;
    const float* xr = x + (size_t)row * DM;
    float* yr = y + (size_t)row * DM;
    int t = threadIdx.x;
    float v[4]; float s = 0.f, ss = 0.f;
#pragma unroll
    for (int i = 0; i < 4; i++) {
        float val = xr[t + i * 256];
        v[i] = val; s += val; ss += val * val;
    }
#pragma unroll
    for (int o = 16; o > 0; o >>= 1) {
        s  += __shfl_xor_sync(0xffffffffu, s, o);
        ss += __shfl_xor_sync(0xffffffffu, ss, o);
    }
    __shared__ float rs[8], rss[8];
    int warp = t >> 5, lane = t & 31;
    if (lane == 0) { rs[warp] = s; rss[warp] = ss; }
    __syncthreads();
    float tot = 0.f, tot2 = 0.f;
#pragma unroll
    for (int i = 0; i < 8; i++) { tot += rs[i]; tot2 += rss[i]; }
    float mean = tot * (1.0f / DM);
    float var  = tot2 * (1.0f / DM) - mean * mean;
    float inv  = rsqrtf(var + 1e-5f);
#pragma unroll
    for (int i = 0; i < 4; i++) {
        int c = t + i * 256;
        yr[c] = (v[i] - mean) * inv * w[c] + b[c];
    }
}

// ---------------- TF32 tensor-core GEMM core (validated round 4) ----------------
template<int EPI>
__device__ __forceinline__ void gemm_tf32_core(
    const float* __restrict__ A, const float* __restrict__ W,
    const float* __restrict__ bias, const float* __restrict__ res,
    float* __restrict__ C, int M, int N, int K, int bm, int bn) {
    __shared__ float As[2][8][136];
    __shared__ float Bs[2][8][136];
    int t = threadIdx.x;
    int lrow = t >> 1, lcol = (t & 1) * 4;
    const float* Ap = A + (size_t)(bm + lrow) * K + lcol;
    const float* Bp = W + (size_t)(bn + lrow) * K + lcol;

    int wid = t >> 5, lane = t & 31;
    int wm = (wid & 1) * 64, wn = (wid >> 1) * 32;
    int g = lane >> 2, t4 = lane & 3;

    float acc[4][4][4];
#pragma unroll
    for (int mi = 0; mi < 4; mi++)
#pragma unroll
        for (int ni = 0; ni < 4; ni++)
#pragma unroll
            for (int r = 0; r < 4; r++) acc[mi][ni][r] = 0.f;

    float4 a4 = *(const float4*)Ap;
    float4 b4 = *(const float4*)Bp;
    As[0][lcol + 0][lrow] = tf32r(a4.x); As[0][lcol + 1][lrow] = tf32r(a4.y);
    As[0][lcol + 2][lrow] = tf32r(a4.z); As[0][lcol + 3][lrow] = tf32r(a4.w);
    Bs[0][lcol + 0][lrow] = tf32r(b4.x); Bs[0][lcol + 1][lrow] = tf32r(b4.y);
    Bs[0][lcol + 2][lrow] = tf32r(b4.z); Bs[0][lcol + 3][lrow] = tf32r(b4.w);
    __syncthreads();
    int buf = 0;
    for (int k0 = 0; k0 < K; k0 += 8) {
        bool has_next = (k0 + 8) < K;
        if (has_next) {
            a4 = *(const float4*)(Ap + k0 + 8);
            b4 = *(const float4*)(Bp + k0 + 8);
        }
        unsigned af[4][4], bf[4][2];
#pragma unroll
        for (int mi = 0; mi < 4; mi++) {
            int m = wm + mi * 16 + g;
            af[mi][0] = __float_as_uint(As[buf][t4][m]);
            af[mi][1] = __float_as_uint(As[buf][t4][m + 8]);
            af[mi][2] = __float_as_uint(As[buf][t4 + 4][m]);
            af[mi][3] = __float_as_uint(As[buf][t4 + 4][m + 8]);
        }
#pragma unroll
        for (int ni = 0; ni < 4; ni++) {
            int n = wn + ni * 8 + g;
            bf[ni][0] = __float_as_uint(Bs[buf][t4][n]);
            bf[ni][1] = __float_as_uint(Bs[buf][t4 + 4][n]);
        }
#pragma unroll
        for (int mi = 0; mi < 4; mi++)
#pragma unroll
            for (int ni = 0; ni < 4; ni++)
                mma_tf32(acc[mi][ni], af[mi], bf[ni]);
        if (has_next) {
            int nb = buf ^ 1;
            As[nb][lcol + 0][lrow] = tf32r(a4.x); As[nb][lcol + 1][lrow] = tf32r(a4.y);
            As[nb][lcol + 2][lrow] = tf32r(a4.z); As[nb][lcol + 3][lrow] = tf32r(a4.w);
            Bs[nb][lcol + 0][lrow] = tf32r(b4.x); Bs[nb][lcol + 1][lrow] = tf32r(b4.y);
            Bs[nb][lcol + 2][lrow] = tf32r(b4.z); Bs[nb][lcol + 3][lrow] = tf32r(b4.w);
            __syncthreads();
            buf = nb;
        }
    }
#pragma unroll
    for (int mi = 0; mi < 4; mi++) {
        int r0 = bm + wm + mi * 16 + g;
#pragma unroll
        for (int ni = 0; ni < 4; ni++) {
            int col = bn + wn + ni * 8 + t4 * 2;
            float b0 = 0.f, b1 = 0.f;
            if (EPI >= 1) {
                float2 bb = *(const float2*)(bias + col);
                b0 = bb.x; b1 = bb.y;
            }
            float v00 = acc[mi][ni][0] + b0, v01 = acc[mi][ni][1] + b1;
            float v10 = acc[mi][ni][2] + b0, v11 = acc[mi][ni][3] + b1;
            if (EPI == 3) {
                v00 = gelu_exact(v00); v01 = gelu_exact(v01);
                v10 = gelu_exact(v10); v11 = gelu_exact(v11);
            }
            if (EPI == 2) {
                float2 r0v = *(const float2*)(res + (size_t)r0 * N + col);
                float2 r1v = *(const float2*)(res + (size_t)(r0 + 8) * N + col);
                v00 += r0v.x; v01 += r0v.y; v10 += r1v.x; v11 += r1v.y;
            }
            *(float2*)(C + (size_t)r0 * N + col)       = make_float2(v00, v01);
            *(float2*)(C + (size_t)(r0 + 8) * N + col) = make_float2(v10, v11);
        }
    }
}

template<int EPI>
__global__ __launch_bounds__(256, 2)
void sgemm_tf32_kernel(const float* __restrict__ A, const float* __restrict__ W,
                       const float* __restrict__ bias, const float* __restrict__ res,
                       float* __restrict__ C, int M, int N, int K) {
    gemm_tf32_core<EPI>(A, W, bias, res, C, M, N, K, blockIdx.y * 128, blockIdx.x * 128);
}

__global__ __launch_bounds__(256, 2)
void sgemm3_tf32_kernel(const float* __restrict__ A,
                        const float* __restrict__ W0, const float* __restrict__ W1,
                        const float* __restrict__ W2,
                        float* __restrict__ C0, float* __restrict__ C1, float* __restrict__ C2,
                        int M, int N, int K) {
    const float* W = (blockIdx.z == 0) ? W0 : (blockIdx.z == 1) ? W1 : W2;
    float* C       = (blockIdx.z == 0) ? C0 : (blockIdx.z == 1) ? C1 : C2;
    gemm_tf32_core<0>(A, W, nullptr, nullptr, C, M, N, K, blockIdx.y * 128, blockIdx.x * 128);
}

// ---------------- QKV stage 2: per-head [N,32]x[32,64] + bias + clamp ----------------
__global__ void qkv2_kernel(const float* __restrict__ Tq, const float* __restrict__ Tk,
                            const float* __restrict__ Tv,
                            const float* __restrict__ Uq, const float* __restrict__ Uk,
                            const float* __restrict__ Uv,
                            const float* __restrict__ bq, const float* __restrict__ bk,
                            const float* __restrict__ bv,
                            float* __restrict__ q, float* __restrict__ k, float* __restrict__ v) {
    int which = blockIdx.z;
    const float* T  = (which == 0) ? Tq : (which == 1) ? Tk : Tv;
    const float* U  = (which == 0) ? Uq : (which == 1) ? Uk : Uv;
    const float* bi = (which == 0) ? bq : (which == 1) ? bk : bv;
    float* outp     = (which == 0) ? q  : (which == 1) ? k  : v;
    int h = blockIdx.y;
    int tok0 = blockIdx.x * 16;
    __shared__ float Us[64][33];
    __shared__ float Ts[16][32];
    int t = threadIdx.x;
    for (int i = t; i < 64 * 32; i += 256) Us[i >> 5][i & 31] = U[(size_t)h * 2048 + i];
    for (int i = t; i < 16 * 32; i += 256)
        Ts[i >> 5][i & 31] = T[(size_t)(tok0 + (i >> 5)) * 512 + h * 32 + (i & 31)];
    __syncthreads();
    int e = t & 63, tg = t >> 6;
    float bsv = bi[h * 64 + e];
#pragma unroll
    for (int ti = 0; ti < 4; ti++) {
        int tok = tg * 4 + ti;
        float s = bsv;
#pragma unroll
        for (int r = 0; r < 32; r++) s += Ts[tok][r] * Us[e][r];
        s = fminf(fmaxf(s, -1.0e6f), 1.0e6f);
        int gtok = tok0 + tok;
        int bb = gtok >> 11;
        int ss = gtok & 2047;
        outp[(((size_t)bb * NH + h) * SEQ + ss) * 64 + e] = s;
    }
}

// ---------------- causal flash attention, TF32 MMA (Br=64, Bc=64, HD=64) ----------------
__global__ __launch_bounds__(128)
void attn_mma_kernel(const float* __restrict__ q, const float* __restrict__ k,
                     const float* __restrict__ v, float* __restrict__ o_) {
    __shared__ float Ks[64 * 64];  // K^T tile: [d][kv], swizzled
    __shared__ float Vs[64 * 64];  // V tile:   [kv][d], swizzled
    __shared__ float Ps[64 * 64];  // P tile:   [q][kv], swizzled (also Q staging)
    int qt = (int)gridDim.x - 1 - (int)blockIdx.x;   // big tiles first
    int h = blockIdx.y, b = blockIdx.z;
    const size_t base = (((size_t)b * NH + h) * SEQ) * 64;
    int t = threadIdx.x, w = t >> 5, lane = t & 31;
    int g = lane >> 2, t4 = lane & 3;
    int row0 = w * 16;
    int rl = row0 + g, rh = row0 + g + 8;       // this thread's two local q-rows
    int qrow_l = qt * 64 + rl, qrow_h = qt * 64 + rh;

    // ---- stage Q tile (warp-local rows) and gather A-fragments ----
    {
        int r = t >> 1, c0 = (t & 1) * 32;      // r in [row0, row0+16) for this warp
        const float4* src = (const float4*)(q + base + (size_t)(qt * 64 + r) * 64 + c0);
#pragma unroll
        for (int i = 0; i < 8; i++) {
            *(float4*)&Ps[r * 64 + SW(r, c0 + i * 4)] = src[i];
        }
    }
    __syncwarp();
    unsigned qf[8][4];
#pragma unroll
    for (int kt = 0; kt < 8; kt++) {
        int d0 = kt * 8 + t4, d1 = d0 + 4;
        qf[kt][0] = __float_as_uint(tf32r(0.125f * Ps[rl * 64 + SW(rl, d0)]));
        qf[kt][1] = __float_as_uint(tf32r(0.125f * Ps[rh * 64 + SW(rh, d0)]));
        qf[kt][2] = __float_as_uint(tf32r(0.125f * Ps[rl * 64 + SW(rl, d1)]));
        qf[kt][3] = __float_as_uint(tf32r(0.125f * Ps[rh * 64 + SW(rh, d1)]));
    }

    float m0 = -1e30f, m1 = -1e30f, l0 = 0.f, l1 = 0.f;
    float oa[8][4];
#pragma unroll
    for (int nt = 0; nt < 8; nt++)
#pragma unroll
        for (int i = 0; i < 4; i++) oa[nt][i] = 0.f;

    int ntiles = qt + 1;
    for (int j = 0; j < ntiles; j++) {
        __syncthreads();   // all warps done reading Ks/Vs of previous tile
        // ---- stage K^T and V (tf32-rounded) ----
        {
            int r = t >> 1, c0 = (t & 1) * 32;
            const float4* ksrc = (const float4*)(k + base + (size_t)(j * 64 + r) * 64 + c0);
            const float4* vsrc = (const float4*)(v + base + (size_t)(j * 64 + r) * 64 + c0);
#pragma unroll
            for (int i = 0; i < 8; i++) {
                int c = c0 + i * 4;
                float4 kv4 = ksrc[i];
                Ks[(c + 0) * 64 + SW(c + 0, r)] = tf32r(kv4.x);
                Ks[(c + 1) * 64 + SW(c + 1, r)] = tf32r(kv4.y);
                Ks[(c + 2) * 64 + SW(c + 2, r)] = tf32r(kv4.z);
                Ks[(c + 3) * 64 + SW(c + 3, r)] = tf32r(kv4.w);
                float4 vv4 = vsrc[i];
                vv4.x = tf32r(vv4.x); vv4.y = tf32r(vv4.y);
                vv4.z = tf32r(vv4.z); vv4.w = tf32r(vv4.w);
                *(float4*)&Vs[r * 64 + SW(r, c)] = vv4;
            }
        }
        __syncthreads();
        // ---- S = Q K^T (scaled) ----
        float s[8][4];
#pragma unroll
        for (int nt = 0; nt < 8; nt++)
#pragma unroll
            for (int i = 0; i < 4; i++) s[nt][i] = 0.f;
#pragma unroll
        for (int kt = 0; kt < 8; kt++) {
            int d0 = kt * 8 + t4, d1 = d0 + 4;
#pragma unroll
            for (int nt = 0; nt < 8; nt++) {
                unsigned bb[2] = { __float_as_uint(Ks[d0 * 64 + SW(d0, nt * 8 + g)]),
                                   __float_as_uint(Ks[d1 * 64 + SW(d1, nt * 8 + g)]) };
                mma_tf32(s[nt], qf[kt], bb);
            }
        }
        // ---- causal mask (diagonal tile only) ----
        if (j == qt) {
#pragma unroll
            for (int nt = 0; nt < 8; nt++) {
                int col = j * 64 + nt * 8 + 2 * t4;
                if (col     > qrow_l) s[nt][0] = -1e30f;
                if (col + 1 > qrow_l) s[nt][1] = -1e30f;
                if (col     > qrow_h) s[nt][2] = -1e30f;
                if (col + 1 > qrow_h) s[nt][3] = -1e30f;
            }
        }
        // ---- online softmax ----
        float rmax0 = -1e30f, rmax1 = -1e30f;
#pragma unroll
        for (int nt = 0; nt < 8; nt++) {
            rmax0 = fmaxf(rmax0, fmaxf(s[nt][0], s[nt][1]));
            rmax1 = fmaxf(rmax1, fmaxf(s[nt][2], s[nt][3]));
        }
        rmax0 = fmaxf(rmax0, __shfl_xor_sync(0xffffffffu, rmax0, 1));
        rmax0 = fmaxf(rmax0, __shfl_xor_sync(0xffffffffu, rmax0, 2));
        rmax1 = fmaxf(rmax1, __shfl_xor_sync(0xffffffffu, rmax1, 1));
        rmax1 = fmaxf(rmax1, __shfl_xor_sync(0xffffffffu, rmax1, 2));
        float mn0 = fmaxf(m0, rmax0), mn1 = fmaxf(m1, rmax1);
        float cr0 = __expf(m0 - mn0), cr1 = __expf(m1 - mn1);
        m0 = mn0; m1 = mn1;
        float rs0 = 0.f, rs1 = 0.f;
#pragma unroll
        for (int nt = 0; nt < 8; nt++) {
            s[nt][0] = __expf(s[nt][0] - mn0);
            s[nt][1] = __expf(s[nt][1] - mn0);
            s[nt][2] = __expf(s[nt][2] - mn1);
            s[nt][3] = __expf(s[nt][3] - mn1);
            rs0 += s[nt][0] + s[nt][1];
            rs1 += s[nt][2] + s[nt][3];
        }
        rs0 += __shfl_xor_sync(0xffffffffu, rs0, 1);
        rs0 += __shfl_xor_sync(0xffffffffu, rs0, 2);
        rs1 += __shfl_xor_sync(0xffffffffu, rs1, 1);
        rs1 += __shfl_xor_sync(0xffffffffu, rs1, 2);
        l0 = l0 * cr0 + rs0;
        l1 = l1 * cr1 + rs1;
#pragma unroll
        for (int nt = 0; nt < 8; nt++) {
            oa[nt][0] *= cr0; oa[nt][1] *= cr0;
            oa[nt][2] *= cr1; oa[nt][3] *= cr1;
        }
        // ---- store P (warp-private rows), refragment as A ----
#pragma unroll
        for (int nt = 0; nt < 8; nt++) {
            int c = nt * 8 + 2 * t4;
            *(float2*)&Ps[rl * 64 + SW(rl, c)] =
                make_float2(tf32r(s[nt][0]), tf32r(s[nt][1]));
            *(float2*)&Ps[rh * 64 + SW(rh, c)] =
                make_float2(tf32r(s[nt][2]), tf32r(s[nt][3]));
        }
        __syncwarp();
        // ---- O += P V ----
#pragma unroll
        for (int kt = 0; kt < 8; kt++) {
            int kv0 = kt * 8 + t4, kv1 = kv0 + 4;
            unsigned af[4] = {
                __float_as_uint(Ps[rl * 64 + SW(rl, kv0)]),
                __float_as_uint(Ps[rh * 64 + SW(rh, kv0)]),
                __float_as_uint(Ps[rl * 64 + SW(rl, kv1)]),
                __float_as_uint(Ps[rh * 64 + SW(rh, kv1)]) };
#pragma unroll
            for (int nt = 0; nt < 8; nt++) {
                unsigned bb[2] = { __float_as_uint(Vs[kv0 * 64 + SW(kv0, nt * 8 + g)]),
                                   __float_as_uint(Vs[kv1 * 64 + SW(kv1, nt * 8 + g)]) };
                mma_tf32(oa[nt], af, bb);
            }
        }
    }
    // ---- epilogue: normalize and write [B*S, D] ----
    float inv0 = 1.0f / l0, inv1 = 1.0f / l1;
#pragma unroll
    for (int nt = 0; nt < 8; nt++) {
        int col = h * 64 + nt * 8 + 2 * t4;
        size_t o0 = (size_t)(b * SEQ + qrow_l) * DM + col;
        size_t o1 = (size_t)(b * SEQ + qrow_h) * DM + col;
        *(float2*)(o_ + o0) = make_float2(oa[nt][0] * inv0, oa[nt][1] * inv0);
        *(float2*)(o_ + o1) = make_float2(oa[nt][2] * inv1, oa[nt][3] * inv1);
    }
}

// ---------------- launch ----------------
extern "C" void kernel_launch(void* const* d_in, const int* in_sizes, int n_in,
                              void* d_out, int out_size) {
    const float* hidden = (const float*)d_in[0];
    const float* q_U    = (const float*)d_in[1];
    const float* q_V    = (const float*)d_in[2];
    const float* q_b    = (const float*)d_in[3];
    const float* k_U    = (const float*)d_in[4];
    const float* k_V    = (const float*)d_in[5];
    const float* k_b    = (const float*)d_in[6];
    const float* v_U    = (const float*)d_in[7];
    const float* v_V    = (const float*)d_in[8];
    const float* v_b    = (const float*)d_in[9];
    const float* out_U  = (const float*)d_in[10];
    const float* out_V  = (const float*)d_in[11];
    const float* out_b  = (const float*)d_in[12];
    const float* fc1_U  = (const float*)d_in[13];
    const float* fc1_V  = (const float*)d_in[14];
    const float* fc1_b  = (const float*)d_in[15];
    const float* fc2_U  = (const float*)d_in[16];
    const float* fc2_V  = (const float*)d_in[17];
    const float* fc2_b  = (const float*)d_in[18];
    const float* ln1w   = (const float*)d_in[19];
    const float* ln1b   = (const float*)d_in[20];
    const float* ln2w   = (const float*)d_in[21];
    const float* ln2b   = (const float*)d_in[22];
    float* out = (float*)d_out;

    float* buf = nullptr;
    cudaGetSymbolAddress((void**)&buf, g_buf);
    float* normed = buf + OFF_NORMED;
    float* Tq = buf + OFF_TQ;  float* Tk = buf + OFF_TK;  float* Tv = buf + OFF_TV;
    float* qd = buf + OFF_Q;   float* kd = buf + OFF_K;   float* vd = buf + OFF_V;
    float* att = buf + OFF_AT;
    float* t1  = buf + OFF_T1;
    float* hb  = buf + OFF_H;
    float* n2  = buf + OFF_N2;
    float* ff  = buf + OFF_FF;
    float* t3  = Tq;

    dim3 gr_r(512 / 128, NTOK / 128);
    dim3 gr_r3(512 / 128, NTOK / 128, 3);
    dim3 gr_d(DM / 128, NTOK / 128);
    dim3 gr_f(INTER_ / 128, NTOK / 128);

    ln_kernel<<<NTOK, 256>>>(hidden, ln1w, ln1b, normed);
    sgemm3_tf32_kernel<<<gr_r3, 256>>>(normed, q_V, k_V, v_V, Tq, Tk, Tv, NTOK, 512, DM);
    qkv2_kernel<<<dim3(NTOK / 16, NH, 3), 256>>>(Tq, Tk, Tv, q_U, k_U, v_U,
                                                 q_b, k_b, v_b, qd, kd, vd);
    attn_mma_kernel<<<dim3(SEQ / 64, NH, BATCH), 128>>>(qd, kd, vd, att);
    sgemm_tf32_kernel<0><<<gr_r, 256>>>(att, out_V, nullptr, nullptr, t1, NTOK, 512, DM);
    sgemm_tf32_kernel<2><<<gr_d, 256>>>(t1, out_U, out_b, hidden, hb, NTOK, DM, 512);
    ln_kernel<<<NTOK, 256>>>(hb, ln2w, ln2b, n2);
    sgemm_tf32_kernel<0><<<gr_r, 256>>>(n2, fc1_V, nullptr, nullptr, t1, NTOK, 512, DM);
    sgemm_tf32_kernel<3><<<gr_f, 256>>>(t1, fc1_U, fc1_b, nullptr, ff, NTOK, INTER_, 512);
    sgemm_tf32_kernel<0><<<gr_r, 256>>>(ff, fc2_V, nullptr, nullptr, t3, NTOK, 512, INTER_);
    sgemm_tf32_kernel<2><<<gr_d, 256>>>(t3, fc2_U, fc2_b, hb, out, NTOK, DM, 512);
}

// round 10
// speedup vs baseline: 2.6121x; 1.2923x over previous
#include <cuda_runtime.h>
#include <cuda_bf16.h>
#include <cstdint>

// Round 10 = third submission of the bf16-GEMM kernel (rounds 8/9 hit broker
// infra failures before any kernel-specific stage; rounds 6/7 prove kernel
// errors DO surface through this pipeline, so the source is not implicated).
// GEMMs: bf16 mma.m16n8k16 fp32-accum; attention: tf32 MMA (validated round 5).

// ---------------- problem dims ----------------
constexpr int NTOK   = 4096;   // B*S
constexpr int BATCH  = 2;
constexpr int SEQ    = 2048;
constexpr int DM     = 1024;
constexpr int NH     = 16;
constexpr int INTER_ = 4096;

constexpr size_t SZ_D  = (size_t)NTOK * DM;
constexpr size_t SZ_R  = (size_t)NTOK * 512;
constexpr size_t SZ_FF = (size_t)NTOK * INTER_;

constexpr size_t OFF_NORMED = 0;
constexpr size_t OFF_TQ = OFF_NORMED + SZ_D;
constexpr size_t OFF_TK = OFF_TQ + SZ_R;
constexpr size_t OFF_TV = OFF_TK + SZ_R;
constexpr size_t OFF_Q  = OFF_TV + SZ_R;
constexpr size_t OFF_K  = OFF_Q + SZ_D;
constexpr size_t OFF_V  = OFF_K + SZ_D;
constexpr size_t OFF_AT = OFF_V + SZ_D;
constexpr size_t OFF_T1 = OFF_AT + SZ_D;
constexpr size_t OFF_H  = OFF_T1 + SZ_R;
constexpr size_t OFF_N2 = OFF_H + SZ_D;
constexpr size_t OFF_FF = OFF_N2 + SZ_D;
constexpr size_t BUF_TOTAL = OFF_FF + SZ_FF;

__device__ float g_buf[BUF_TOTAL];

// ---------------- helpers ----------------
__device__ __forceinline__ float gelu_exact(float x) {
    return 0.5f * x * (1.0f + erff(x * 0.7071067811865476f));
}
__device__ __forceinline__ float tf32r(float f) {
    unsigned u;
    asm("cvt.rna.tf32.f32 %0, %1;" : "=r"(u) : "f"(f));
    return __uint_as_float(u);
}
__device__ __forceinline__ uint32_t bf2(float lo, float hi) {
    __nv_bfloat162 h = __floats2bfloat162_rn(lo, hi);
    return *(uint32_t*)&h;
}
__device__ __forceinline__ void mma_tf32(float* c, const unsigned* a, const unsigned* b) {
    asm volatile(
        "mma.sync.aligned.m16n8k8.row.col.f32.tf32.tf32.f32 "
        "{%0,%1,%2,%3}, {%4,%5,%6,%7}, {%8,%9}, {%0,%1,%2,%3};"
        : "+f"(c[0]), "+f"(c[1]), "+f"(c[2]), "+f"(c[3])
        : "r"(a[0]), "r"(a[1]), "r"(a[2]), "r"(a[3]), "r"(b[0]), "r"(b[1]));
}
__device__ __forceinline__ void mma_bf16(float* c, const unsigned* a, const unsigned* b) {
    asm volatile(
        "mma.sync.aligned.m16n8k16.row.col.f32.bf16.bf16.f32 "
        "{%0,%1,%2,%3}, {%4,%5,%6,%7}, {%8,%9}, {%0,%1,%2,%3};"
        : "+f"(c[0]), "+f"(c[1]), "+f"(c[2]), "+f"(c[3])
        : "r"(a[0]), "r"(a[1]), "r"(a[2]), "r"(a[3]), "r"(b[0]), "r"(b[1]));
}
#define SW(r, c) ((c) ^ (((r) & 3) << 3))   // attention smem swizzle (64-float rows)

// ---------------- LayerNorm ----------------
__global__ void ln_kernel(const float* __restrict__ x, const float* __restrict__ w,
                          const float* __restrict__ b, float* __restrict__ y) {
    int row = blockIdx.x;
    const float* xr = x + (size_t)row * DM;
    float* yr = y + (size_t)row * DM;
    int t = threadIdx.x;
    float v[4]; float s = 0.f, ss = 0.f;
#pragma unroll
    for (int i = 0; i < 4; i++) {
        float val = xr[t + i * 256];
        v[i] = val; s += val; ss += val * val;
    }
#pragma unroll
    for (int o = 16; o > 0; o >>= 1) {
        s  += __shfl_xor_sync(0xffffffffu, s, o);
        ss += __shfl_xor_sync(0xffffffffu, ss, o);
    }
    __shared__ float rs[8], rss[8];
    int warp = t >> 5, lane = t & 31;
    if (lane == 0) { rs[warp] = s; rss[warp] = ss; }
    __syncthreads();
    float tot = 0.f, tot2 = 0.f;
#pragma unroll
    for (int i = 0; i < 8; i++) { tot += rs[i]; tot2 += rss[i]; }
    float mean = tot * (1.0f / DM);
    float var  = tot2 * (1.0f / DM) - mean * mean;
    float inv  = rsqrtf(var + 1e-5f);
#pragma unroll
    for (int i = 0; i < 4; i++) {
        int c = t + i * 256;
        yr[c] = (v[i] - mean) * inv * w[c] + b[c];
    }
}

// ---------------- bf16 tensor-core GEMM core ----------------
// C[M,N] = A[M,K] @ W[N,K]^T ; block 128x128, 8 warps (2x4), warp tile 64x32,
// k-slab 16 (8 bf16-pairs), double-buffered. Each uint32 in smem = 2 bf16
// (consecutive K). Fragment indexing identical to the validated tf32 core.
// EPI: 0 none, 1 +bias, 2 +bias+res, 3 gelu(acc+bias)
template<int EPI>
__device__ __forceinline__ void gemm_bf16_core(
    const float* __restrict__ A, const float* __restrict__ W,
    const float* __restrict__ bias, const float* __restrict__ res,
    float* __restrict__ C, int M, int N, int K, int bm, int bn) {
    __shared__ uint32_t As[2][8][136];
    __shared__ uint32_t Bs[2][8][136];
    int t = threadIdx.x;
    int lrow = t >> 1;            // 0..127
    int lp0  = (t & 1) * 4;       // 4 K-pairs per thread: pairs lp0..lp0+3
    const float* Ap = A + (size_t)(bm + lrow) * K + lp0 * 2;
    const float* Bp = W + (size_t)(bn + lrow) * K + lp0 * 2;

    int wid = t >> 5, lane = t & 31;
    int wm = (wid & 1) * 64, wn = (wid >> 1) * 32;
    int g = lane >> 2, t4 = lane & 3;

    float acc[4][4][4];
#pragma unroll
    for (int mi = 0; mi < 4; mi++)
#pragma unroll
        for (int ni = 0; ni < 4; ni++)
#pragma unroll
            for (int r = 0; r < 4; r++) acc[mi][ni][r] = 0.f;

    float4 a0 = *(const float4*)Ap, a1 = *(const float4*)(Ap + 4);
    float4 b0 = *(const float4*)Bp, b1 = *(const float4*)(Bp + 4);
    As[0][lp0 + 0][lrow] = bf2(a0.x, a0.y); As[0][lp0 + 1][lrow] = bf2(a0.z, a0.w);
    As[0][lp0 + 2][lrow] = bf2(a1.x, a1.y); As[0][lp0 + 3][lrow] = bf2(a1.z, a1.w);
    Bs[0][lp0 + 0][lrow] = bf2(b0.x, b0.y); Bs[0][lp0 + 1][lrow] = bf2(b0.z, b0.w);
    Bs[0][lp0 + 2][lrow] = bf2(b1.x, b1.y); Bs[0][lp0 + 3][lrow] = bf2(b1.z, b1.w);
    __syncthreads();
    int buf = 0;
    for (int k0 = 0; k0 < K; k0 += 16) {
        bool has_next = (k0 + 16) < K;
        if (has_next) {
            a0 = *(const float4*)(Ap + k0 + 16); a1 = *(const float4*)(Ap + k0 + 20);
            b0 = *(const float4*)(Bp + k0 + 16); b1 = *(const float4*)(Bp + k0 + 20);
        }
        unsigned af[4][4], bf[4][2];
#pragma unroll
        for (int mi = 0; mi < 4; mi++) {
            int m = wm + mi * 16 + g;
            af[mi][0] = As[buf][t4][m];
            af[mi][1] = As[buf][t4][m + 8];
            af[mi][2] = As[buf][t4 + 4][m];
            af[mi][3] = As[buf][t4 + 4][m + 8];
        }
#pragma unroll
        for (int ni = 0; ni < 4; ni++) {
            int n = wn + ni * 8 + g;
            bf[ni][0] = Bs[buf][t4][n];
            bf[ni][1] = Bs[buf][t4 + 4][n];
        }
#pragma unroll
        for (int mi = 0; mi < 4; mi++)
#pragma unroll
            for (int ni = 0; ni < 4; ni++)
                mma_bf16(acc[mi][ni], af[mi], bf[ni]);
        if (has_next) {
            int nb = buf ^ 1;
            As[nb][lp0 + 0][lrow] = bf2(a0.x, a0.y); As[nb][lp0 + 1][lrow] = bf2(a0.z, a0.w);
            As[nb][lp0 + 2][lrow] = bf2(a1.x, a1.y); As[nb][lp0 + 3][lrow] = bf2(a1.z, a1.w);
            Bs[nb][lp0 + 0][lrow] = bf2(b0.x, b0.y); Bs[nb][lp0 + 1][lrow] = bf2(b0.z, b0.w);
            Bs[nb][lp0 + 2][lrow] = bf2(b1.x, b1.y); Bs[nb][lp0 + 3][lrow] = bf2(b1.z, b1.w);
            __syncthreads();
            buf = nb;
        }
    }
    // epilogue: c0,c1 at (row, col..col+1); c2,c3 at (row+8, col..col+1)
#pragma unroll
    for (int mi = 0; mi < 4; mi++) {
        int r0 = bm + wm + mi * 16 + g;
#pragma unroll
        for (int ni = 0; ni < 4; ni++) {
            int col = bn + wn + ni * 8 + t4 * 2;
            float bb0 = 0.f, bb1 = 0.f;
            if (EPI >= 1) {
                float2 bb = *(const float2*)(bias + col);
                bb0 = bb.x; bb1 = bb.y;
            }
            float v00 = acc[mi][ni][0] + bb0, v01 = acc[mi][ni][1] + bb1;
            float v10 = acc[mi][ni][2] + bb0, v11 = acc[mi][ni][3] + bb1;
            if (EPI == 3) {
                v00 = gelu_exact(v00); v01 = gelu_exact(v01);
                v10 = gelu_exact(v10); v11 = gelu_exact(v11);
            }
            if (EPI == 2) {
                float2 r0v = *(const float2*)(res + (size_t)r0 * N + col);
                float2 r1v = *(const float2*)(res + (size_t)(r0 + 8) * N + col);
                v00 += r0v.x; v01 += r0v.y; v10 += r1v.x; v11 += r1v.y;
            }
            *(float2*)(C + (size_t)r0 * N + col)       = make_float2(v00, v01);
            *(float2*)(C + (size_t)(r0 + 8) * N + col) = make_float2(v10, v11);
        }
    }
}

template<int EPI>
__global__ __launch_bounds__(256, 2)
void sgemm_bf16_kernel(const float* __restrict__ A, const float* __restrict__ W,
                       const float* __restrict__ bias, const float* __restrict__ res,
                       float* __restrict__ C, int M, int N, int K) {
    gemm_bf16_core<EPI>(A, W, bias, res, C, M, N, K, blockIdx.y * 128, blockIdx.x * 128);
}

__global__ __launch_bounds__(256, 2)
void sgemm3_bf16_kernel(const float* __restrict__ A,
                        const float* __restrict__ W0, const float* __restrict__ W1,
                        const float* __restrict__ W2,
                        float* __restrict__ C0, float* __restrict__ C1, float* __restrict__ C2,
                        int M, int N, int K) {
    const float* W = (blockIdx.z == 0) ? W0 : (blockIdx.z == 1) ? W1 : W2;
    float* C       = (blockIdx.z == 0) ? C0 : (blockIdx.z == 1) ? C1 : C2;
    gemm_bf16_core<0>(A, W, nullptr, nullptr, C, M, N, K, blockIdx.y * 128, blockIdx.x * 128);
}

// ---------------- QKV stage 2: per-head [N,32]x[32,64] + bias + clamp ----------------
__global__ void qkv2_kernel(const float* __restrict__ Tq, const float* __restrict__ Tk,
                            const float* __restrict__ Tv,
                            const float* __restrict__ Uq, const float* __restrict__ Uk,
                            const float* __restrict__ Uv,
                            const float* __restrict__ bq, const float* __restrict__ bk,
                            const float* __restrict__ bv,
                            float* __restrict__ q, float* __restrict__ k, float* __restrict__ v) {
    int which = blockIdx.z;
    const float* T  = (which == 0) ? Tq : (which == 1) ? Tk : Tv;
    const float* U  = (which == 0) ? Uq : (which == 1) ? Uk : Uv;
    const float* bi = (which == 0) ? bq : (which == 1) ? bk : bv;
    float* outp     = (which == 0) ? q  : (which == 1) ? k  : v;
    int h = blockIdx.y;
    int tok0 = blockIdx.x * 16;
    __shared__ float Us[64][33];
    __shared__ float Ts[16][32];
    int t = threadIdx.x;
    for (int i = t; i < 64 * 32; i += 256) Us[i >> 5][i & 31] = U[(size_t)h * 2048 + i];
    for (int i = t; i < 16 * 32; i += 256)
        Ts[i >> 5][i & 31] = T[(size_t)(tok0 + (i >> 5)) * 512 + h * 32 + (i & 31)];
    __syncthreads();
    int e = t & 63, tg = t >> 6;
    float bsv = bi[h * 64 + e];
#pragma unroll
    for (int ti = 0; ti < 4; ti++) {
        int tok = tg * 4 + ti;
        float s = bsv;
#pragma unroll
        for (int r = 0; r < 32; r++) s += Ts[tok][r] * Us[e][r];
        s = fminf(fmaxf(s, -1.0e6f), 1.0e6f);
        int gtok = tok0 + tok;
        int bb = gtok >> 11;
        int ss = gtok & 2047;
        outp[(((size_t)bb * NH + h) * SEQ + ss) * 64 + e] = s;
    }
}

// ---------------- causal flash attention, TF32 MMA (validated round 5) ----------------
__global__ __launch_bounds__(128)
void attn_mma_kernel(const float* __restrict__ q, const float* __restrict__ k,
                     const float* __restrict__ v, float* __restrict__ o_) {
    __shared__ float Ks[64 * 64];
    __shared__ float Vs[64 * 64];
    __shared__ float Ps[64 * 64];
    int qt = (int)gridDim.x - 1 - (int)blockIdx.x;
    int h = blockIdx.y, b = blockIdx.z;
    const size_t base = (((size_t)b * NH + h) * SEQ) * 64;
    int t = threadIdx.x, w = t >> 5, lane = t & 31;
    int g = lane >> 2, t4 = lane & 3;
    int row0 = w * 16;
    int rl = row0 + g, rh = row0 + g + 8;
    int qrow_l = qt * 64 + rl, qrow_h = qt * 64 + rh;

    {
        int r = t >> 1, c0 = (t & 1) * 32;
        const float4* src = (const float4*)(q + base + (size_t)(qt * 64 + r) * 64 + c0);
#pragma unroll
        for (int i = 0; i < 8; i++) {
            *(float4*)&Ps[r * 64 + SW(r, c0 + i * 4)] = src[i];
        }
    }
    __syncwarp();
    unsigned qf[8][4];
#pragma unroll
    for (int kt = 0; kt < 8; kt++) {
        int d0 = kt * 8 + t4, d1 = d0 + 4;
        qf[kt][0] = __float_as_uint(tf32r(0.125f * Ps[rl * 64 + SW(rl, d0)]));
        qf[kt][1] = __float_as_uint(tf32r(0.125f * Ps[rh * 64 + SW(rh, d0)]));
        qf[kt][2] = __float_as_uint(tf32r(0.125f * Ps[rl * 64 + SW(rl, d1)]));
        qf[kt][3] = __float_as_uint(tf32r(0.125f * Ps[rh * 64 + SW(rh, d1)]));
    }

    float m0 = -1e30f, m1 = -1e30f, l0 = 0.f, l1 = 0.f;
    float oa[8][4];
#pragma unroll
    for (int nt = 0; nt < 8; nt++)
#pragma unroll
        for (int i = 0; i < 4; i++) oa[nt][i] = 0.f;

    int ntiles = qt + 1;
    for (int j = 0; j < ntiles; j++) {
        __syncthreads();
        {
            int r = t >> 1, c0 = (t & 1) * 32;
            const float4* ksrc = (const float4*)(k + base + (size_t)(j * 64 + r) * 64 + c0);
            const float4* vsrc = (const float4*)(v + base + (size_t)(j * 64 + r) * 64 + c0);
#pragma unroll
            for (int i = 0; i < 8; i++) {
                int c = c0 + i * 4;
                float4 kv4 = ksrc[i];
                Ks[(c + 0) * 64 + SW(c + 0, r)] = tf32r(kv4.x);
                Ks[(c + 1) * 64 + SW(c + 1, r)] = tf32r(kv4.y);
                Ks[(c + 2) * 64 + SW(c + 2, r)] = tf32r(kv4.z);
                Ks[(c + 3) * 64 + SW(c + 3, r)] = tf32r(kv4.w);
                float4 vv4 = vsrc[i];
                vv4.x = tf32r(vv4.x); vv4.y = tf32r(vv4.y);
                vv4.z = tf32r(vv4.z); vv4.w = tf32r(vv4.w);
                *(float4*)&Vs[r * 64 + SW(r, c)] = vv4;
            }
        }
        __syncthreads();
        float s[8][4];
#pragma unroll
        for (int nt = 0; nt < 8; nt++)
#pragma unroll
            for (int i = 0; i < 4; i++) s[nt][i] = 0.f;
#pragma unroll
        for (int kt = 0; kt < 8; kt++) {
            int d0 = kt * 8 + t4, d1 = d0 + 4;
#pragma unroll
            for (int nt = 0; nt < 8; nt++) {
                unsigned bb[2] = { __float_as_uint(Ks[d0 * 64 + SW(d0, nt * 8 + g)]),
                                   __float_as_uint(Ks[d1 * 64 + SW(d1, nt * 8 + g)]) };
                mma_tf32(s[nt], qf[kt], bb);
            }
        }
        if (j == qt) {
#pragma unroll
            for (int nt = 0; nt < 8; nt++) {
                int col = j * 64 + nt * 8 + 2 * t4;
                if (col     > qrow_l) s[nt][0] = -1e30f;
                if (col + 1 > qrow_l) s[nt][1] = -1e30f;
                if (col     > qrow_h) s[nt][2] = -1e30f;
                if (col + 1 > qrow_h) s[nt][3] = -1e30f;
            }
        }
        float rmax0 = -1e30f, rmax1 = -1e30f;
#pragma unroll
        for (int nt = 0; nt < 8; nt++) {
            rmax0 = fmaxf(rmax0, fmaxf(s[nt][0], s[nt][1]));
            rmax1 = fmaxf(rmax1, fmaxf(s[nt][2], s[nt][3]));
        }
        rmax0 = fmaxf(rmax0, __shfl_xor_sync(0xffffffffu, rmax0, 1));
        rmax0 = fmaxf(rmax0, __shfl_xor_sync(0xffffffffu, rmax0, 2));
        rmax1 = fmaxf(rmax1, __shfl_xor_sync(0xffffffffu, rmax1, 1));
        rmax1 = fmaxf(rmax1, __shfl_xor_sync(0xffffffffu, rmax1, 2));
        float mn0 = fmaxf(m0, rmax0), mn1 = fmaxf(m1, rmax1);
        float cr0 = __expf(m0 - mn0), cr1 = __expf(m1 - mn1);
        m0 = mn0; m1 = mn1;
        float rs0 = 0.f, rs1 = 0.f;
#pragma unroll
        for (int nt = 0; nt < 8; nt++) {
            s[nt][0] = __expf(s[nt][0] - mn0);
            s[nt][1] = __expf(s[nt][1] - mn0);
            s[nt][2] = __expf(s[nt][2] - mn1);
            s[nt][3] = __expf(s[nt][3] - mn1);
            rs0 += s[nt][0] + s[nt][1];
            rs1 += s[nt][2] + s[nt][3];
        }
        rs0 += __shfl_xor_sync(0xffffffffu, rs0, 1);
        rs0 += __shfl_xor_sync(0xffffffffu, rs0, 2);
        rs1 += __shfl_xor_sync(0xffffffffu, rs1, 1);
        rs1 += __shfl_xor_sync(0xffffffffu, rs1, 2);
        l0 = l0 * cr0 + rs0;
        l1 = l1 * cr1 + rs1;
#pragma unroll
        for (int nt = 0; nt < 8; nt++) {
            oa[nt][0] *= cr0; oa[nt][1] *= cr0;
            oa[nt][2] *= cr1; oa[nt][3] *= cr1;
        }
#pragma unroll
        for (int nt = 0; nt < 8; nt++) {
            int c = nt * 8 + 2 * t4;
            *(float2*)&Ps[rl * 64 + SW(rl, c)] =
                make_float2(tf32r(s[nt][0]), tf32r(s[nt][1]));
            *(float2*)&Ps[rh * 64 + SW(rh, c)] =
                make_float2(tf32r(s[nt][2]), tf32r(s[nt][3]));
        }
        __syncwarp();
#pragma unroll
        for (int kt = 0; kt < 8; kt++) {
            int kv0 = kt * 8 + t4, kv1 = kv0 + 4;
            unsigned af[4] = {
                __float_as_uint(Ps[rl * 64 + SW(rl, kv0)]),
                __float_as_uint(Ps[rh * 64 + SW(rh, kv0)]),
                __float_as_uint(Ps[rl * 64 + SW(rl, kv1)]),
                __float_as_uint(Ps[rh * 64 + SW(rh, kv1)]) };
#pragma unroll
            for (int nt = 0; nt < 8; nt++) {
                unsigned bb[2] = { __float_as_uint(Vs[kv0 * 64 + SW(kv0, nt * 8 + g)]),
                                   __float_as_uint(Vs[kv1 * 64 + SW(kv1, nt * 8 + g)]) };
                mma_tf32(oa[nt], af, bb);
            }
        }
    }
    float inv0 = 1.0f / l0, inv1 = 1.0f / l1;
#pragma unroll
    for (int nt = 0; nt < 8; nt++) {
        int col = h * 64 + nt * 8 + 2 * t4;
        size_t o0 = (size_t)(b * SEQ + qrow_l) * DM + col;
        size_t o1 = (size_t)(b * SEQ + qrow_h) * DM + col;
        *(float2*)(o_ + o0) = make_float2(oa[nt][0] * inv0, oa[nt][1] * inv0);
        *(float2*)(o_ + o1) = make_float2(oa[nt][2] * inv1, oa[nt][3] * inv1);
    }
}

// ---------------- launch ----------------
extern "C" void kernel_launch(void* const* d_in, const int* in_sizes, int n_in,
                              void* d_out, int out_size) {
    const float* hidden = (const float*)d_in[0];
    const float* q_U    = (const float*)d_in[1];
    const float* q_V    = (const float*)d_in[2];
    const float* q_b    = (const float*)d_in[3];
    const float* k_U    = (const float*)d_in[4];
    const float* k_V    = (const float*)d_in[5];
    const float* k_b    = (const float*)d_in[6];
    const float* v_U    = (const float*)d_in[7];
    const float* v_V    = (const float*)d_in[8];
    const float* v_b    = (const float*)d_in[9];
    const float* out_U  = (const float*)d_in[10];
    const float* out_V  = (const float*)d_in[11];
    const float* out_b  = (const float*)d_in[12];
    const float* fc1_U  = (const float*)d_in[13];
    const float* fc1_V  = (const float*)d_in[14];
    const float* fc1_b  = (const float*)d_in[15];
    const float* fc2_U  = (const float*)d_in[16];
    const float* fc2_V  = (const float*)d_in[17];
    const float* fc2_b  = (const float*)d_in[18];
    const float* ln1w   = (const float*)d_in[19];
    const float* ln1b   = (const float*)d_in[20];
    const float* ln2w   = (const float*)d_in[21];
    const float* ln2b   = (const float*)d_in[22];
    float* out = (float*)d_out;

    float* buf = nullptr;
    cudaGetSymbolAddress((void**)&buf, g_buf);
    float* normed = buf + OFF_NORMED;
    float* Tq = buf + OFF_TQ;  float* Tk = buf + OFF_TK;  float* Tv = buf + OFF_TV;
    float* qd = buf + OFF_Q;   float* kd = buf + OFF_K;   float* vd = buf + OFF_V;
    float* att = buf + OFF_AT;
    float* t1  = buf + OFF_T1;
    float* hb  = buf + OFF_H;
    float* n2  = buf + OFF_N2;
    float* ff  = buf + OFF_FF;
    float* t3  = Tq;

    dim3 gr_r(512 / 128, NTOK / 128);
    dim3 gr_r3(512 / 128, NTOK / 128, 3);
    dim3 gr_d(DM / 128, NTOK / 128);
    dim3 gr_f(INTER_ / 128, NTOK / 128);

    ln_kernel<<<NTOK, 256>>>(hidden, ln1w, ln1b, normed);
    sgemm3_bf16_kernel<<<gr_r3, 256>>>(normed, q_V, k_V, v_V, Tq, Tk, Tv, NTOK, 512, DM);
    qkv2_kernel<<<dim3(NTOK / 16, NH, 3), 256>>>(Tq, Tk, Tv, q_U, k_U, v_U,
                                                 q_b, k_b, v_b, qd, kd, vd);
    attn_mma_kernel<<<dim3(SEQ / 64, NH, BATCH), 128>>>(qd, kd, vd, att);
    sgemm_bf16_kernel<0><<<gr_r, 256>>>(att, out_V, nullptr, nullptr, t1, NTOK, 512, DM);
    sgemm_bf16_kernel<2><<<gr_d, 256>>>(t1, out_U, out_b, hidden, hb, NTOK, DM, 512);
    ln_kernel<<<NTOK, 256>>>(hb, ln2w, ln2b, n2);
    sgemm_bf16_kernel<0><<<gr_r, 256>>>(n2, fc1_V, nullptr, nullptr, t1, NTOK, 512, DM);
    sgemm_bf16_kernel<3><<<gr_f, 256>>>(t1, fc1_U, fc1_b, nullptr, ff, NTOK, INTER_, 512);
    sgemm_bf16_kernel<0><<<gr_r, 256>>>(ff, fc2_V, nullptr, nullptr, t3, NTOK, 512, INTER_);
    sgemm_bf16_kernel<2><<<gr_d, 256>>>(t3, fc2_U, fc2_b, hb, out, NTOK, DM, 512);
}